// round 13
// baseline (speedup 1.0000x reference)
#include <cuda_runtime.h>
#include <cuda_bf16.h>
#include <cstdint>

#define Nn 64
#define Cc 64
#define Tt 300
#define Vv 25
#define ICn 16
#define Pp 7500      // T*V
#define SLOTS 144
#define ROWS1 80
#define ROWS9 64

// ---------------- device scratch (static; no allocations) ----------------
__device__ __nv_bfloat16 g_Fb[2][Nn][SLOTS][Pp];   // features (bf16), both sides
__device__ float g_z[Nn][3][Cc][Pp];
__device__ float g_y[Nn][Cc][Pp];
__device__ float g_S[Nn][9][Vv][Vv];
__device__ float g_Ai[Nn][3][Vv][Vv];
__device__ float g_Amix[3][Vv][Vv];
__device__ float g_W1[2][ROWS1][Cc];
__device__ float g_B1[2][ROWS1];
__device__ float g_B9[2][ROWS9];
__device__ float g_part[Cc][Nn][2];
__device__ float g_bn[Cc][2];

// bf16 data for HMMA kernels
__device__ uint4 g_W9h4[9][128][8];     // [tap][row(side*64+r)][64 bf16 channels]
__device__ uint4 g_W1b4[192][8];        // packed 1x1 weights, rows 0..159 real
__device__ uint4 g_xTh4[Nn][Pp][8];     // transposed x: [n][p][64 c] bf16

// ================= helpers =================
__device__ __forceinline__ uint32_t smem_u32(const void* p) {
    uint32_t a;
    asm("{ .reg .u64 t; cvta.to.shared.u64 t, %1; cvt.u32.u64 %0, t; }" : "=r"(a) : "l"(p));
    return a;
}

__device__ __forceinline__ void ldsm_x4(uint32_t addr, uint32_t* r) {
    asm volatile("ldmatrix.sync.aligned.m8n8.x4.shared.b16 {%0,%1,%2,%3}, [%4];"
        : "=r"(r[0]), "=r"(r[1]), "=r"(r[2]), "=r"(r[3]) : "r"(addr));
}
__device__ __forceinline__ void ldsm_x4t(uint32_t addr, uint32_t* r) {
    asm volatile("ldmatrix.sync.aligned.m8n8.x4.trans.shared.b16 {%0,%1,%2,%3}, [%4];"
        : "=r"(r[0]), "=r"(r[1]), "=r"(r[2]), "=r"(r[3]) : "r"(addr));
}
__device__ __forceinline__ void mma16816(float* d, const uint32_t* a, uint32_t b0, uint32_t b1) {
    asm volatile("mma.sync.aligned.m16n8k16.row.col.f32.bf16.bf16.f32 "
        "{%0,%1,%2,%3}, {%4,%5,%6,%7}, {%8,%9}, {%0,%1,%2,%3};"
        : "+f"(d[0]), "+f"(d[1]), "+f"(d[2]), "+f"(d[3])
        : "r"(a[0]), "r"(a[1]), "r"(a[2]), "r"(a[3]), "r"(b0), "r"(b1));
}

// ---------------- weight packing (fp32 parts) ----------------
__global__ void pack_kernel(const float* a_w, const float* a_b,
                            const float* b_w, const float* b_b,
                            const float* t1_b, const float* t2_b,
                            const float* st11_w1x1, const float* st11_b,
                            const float* st12_w1x1, const float* st12_b) {
    int tid = blockIdx.x * blockDim.x + threadIdx.x;
    int stride = gridDim.x * blockDim.x;
    for (int idx = tid; idx < 2 * ROWS1 * Cc; idx += stride) {
        int side = idx / (ROWS1 * Cc);
        int r = (idx / Cc) % ROWS1;
        int c = idx % Cc;
        const float* wab = side ? b_w : a_w;
        const float* wst = side ? st12_w1x1 : st11_w1x1;
        float v;
        if (r < 48)       v = wab[r * Cc + c];
        else if (r < 64)  v = wst[(0 * ICn + (r - 48)) * Cc + c];
        else              v = wst[(1 * ICn + (r - 64)) * Cc + c];
        g_W1[side][r][c] = v;
    }
    for (int idx = tid; idx < 2 * ROWS1; idx += stride) {
        int side = idx / ROWS1; int r = idx % ROWS1;
        const float* bab = side ? b_b : a_b;
        const float* bst = side ? st12_b : st11_b;
        float v;
        if (r < 48)       v = bab[r];
        else if (r < 64)  v = bst[0 * ICn + (r - 48)];
        else              v = bst[2 * ICn + (r - 64)];
        g_B1[side][r] = v;
    }
    for (int idx = tid; idx < 2 * ROWS9; idx += stride) {
        int side = idx / ROWS9; int r = idx % ROWS9;
        const float* bt = side ? t2_b : t1_b;
        const float* bst = side ? st12_b : st11_b;
        g_B9[side][r] = (r < 48) ? bt[r] : bst[1 * ICn + (r - 48)];
    }
}

// ---------------- W9 bf16 pack, tap-major ----------------
__global__ void w9pack_kernel(const float* t1_w, const float* t2_w,
                              const float* st11_w9, const float* st12_w9) {
    int idx = blockIdx.x * 256 + threadIdx.x;
    if (idx >= 9 * 128 * 64) return;
    int k = idx / (128 * 64);
    int r = (idx / 64) % 128;
    int c = idx % 64;
    int side = r >> 6, rr = r & 63;
    const float* wt = side ? t2_w : t1_w;
    const float* wstc = side ? st12_w9 : st11_w9;
    float w = (rr < 48) ? wt[(rr * 64 + c) * 9 + k] : wstc[((rr - 48) * 64 + c) * 9 + k];
    ((__nv_bfloat16*)g_W9h4)[(k * 128 + r) * 64 + c] = __float2bfloat16_rn(w);
}

// ---------------- W1 bf16 pack ----------------
__global__ void w1bpack_kernel() {
    int idx = blockIdx.x * 256 + threadIdx.x;
    if (idx >= 192 * 64) return;
    int r = idx / 64, c = idx % 64;
    float v = 0.f;
    if (r < 160) {
        int side = r / 80, rr = r % 80;
        v = g_W1[side][rr][c];
    }
    ((__nv_bfloat16*)g_W1b4)[r * 64 + c] = __float2bfloat16_rn(v);
}

// ---------------- x transpose + bf16 (vectorized stores) ----------------
__global__ void xsplit_kernel(const float* __restrict__ x) {
    __shared__ float s[64][65];
    int p0 = blockIdx.x * 64;
    int n = blockIdx.y;
    int tid = threadIdx.x;
    for (int i = tid; i < 4096; i += 256) {
        int c = i >> 6, j = i & 63;
        int p = p0 + j;
        s[c][j] = (p < Pp) ? x[((size_t)n * 64 + c) * Pp + p] : 0.f;
    }
    __syncthreads();
    __nv_bfloat162* oh2 = (__nv_bfloat162*)g_xTh4;
    for (int i = tid; i < 2048; i += 256) {
        int j = i >> 5, ch = i & 31;   // ch = c/2
        int p = p0 + j;
        if (p < Pp) {
            int c = ch * 2;
            __nv_bfloat162 v = __floats2bfloat162_rn(s[c][j], s[c + 1][j]);
            oh2[((size_t)n * Pp + p) * 32 + ch] = v;
        }
    }
}

// ---------------- A_mix ----------------
__global__ void amix_kernel(const float* A, const float* weights) {
    int i = blockIdx.x;
    int tid = threadIdx.x;
    int u = tid / 25, v = tid % 25;
    __shared__ float ch4sm[25][25];
    __shared__ float colmax[25], colsum[25];
    float a = A[i * 625 + tid];
    float a2 = a * a, a3 = a2 * a, a4 = a2 * a2;
    float eye = (u == v) ? 1.f : 0.f;
    float ch4 = 8.f * a4 - 8.f * a2 + eye;
    float ch3 = 4.f * a3 - 3.f * a;
    float ch2 = 2.f * a2 - eye;
    ch4sm[u][v] = ch4 / 25.f;
    __syncthreads();
    if (tid < 25) {
        float m = -1e30f;
        for (int uu = 0; uu < 25; uu++) m = fmaxf(m, ch4sm[uu][tid]);
        float s = 0.f;
        for (int uu = 0; uu < 25; uu++) s += expf(ch4sm[uu][tid] - m);
        colmax[tid] = m; colsum[tid] = s;
    }
    __syncthreads();
    float ch4s = expf(ch4 / 25.f - colmax[v]) / colsum[v];
    g_Amix[i][u][v] = weights[0] * a + weights[1] * ch4s + weights[2] * ch4
                    + weights[3] * ch3 + weights[4] * ch2;
}

// ---------------- conv1x1 via HMMA ----------------
__global__ void conv1x1_hmma_kernel() {
    __shared__ __align__(16) __nv_bfloat16 As[192 * 72];
    __shared__ __align__(16) __nv_bfloat16 Bs[128 * 72];
    int p0 = blockIdx.x * 128;
    int n = blockIdx.y;
    int tid = threadIdx.x;
    int wid = tid >> 5, lane = tid & 31;
    int g8 = lane >> 3, r8 = lane & 7;
    int grp = lane >> 2, tig = lane & 3;
    int m_base = (wid % 6) * 32;
    int n_base = (wid / 6) * 64;

    uint32_t Asb = smem_u32(As);
    uint32_t Bsb = smem_u32(Bs);
    uint32_t a_off = (uint32_t)(m_base + ((g8 & 1) << 3) + r8) * 144 + ((g8 >> 1) << 4);
    uint32_t b_off = (uint32_t)(n_base + ((g8 & 2) << 2) + r8) * 144 + ((g8 & 1) << 4);

    const uint4* xh = &g_xTh4[n][0][0];
    for (int i = tid; i < 1536; i += 384) {
        int row = i >> 3, ch = i & 7;
        *(uint4*)((char*)As + row * 144 + ch * 16) = g_W1b4[row][ch];
    }
    for (int i = tid; i < 1024; i += 384) {
        int row = i >> 3, ch = i & 7;
        int p = p0 + row;
        uint4 v = (p < Pp) ? xh[(size_t)p * 8 + ch] : make_uint4(0, 0, 0, 0);
        *(uint4*)((char*)Bs + row * 144 + ch * 16) = v;
    }
    __syncthreads();

    float acc[2][8][4];
    #pragma unroll
    for (int mi = 0; mi < 2; mi++)
        #pragma unroll
        for (int nj = 0; nj < 8; nj++)
            #pragma unroll
            for (int e = 0; e < 4; e++) acc[mi][nj][e] = 0.f;

    #pragma unroll
    for (int ks = 0; ks < 4; ks++) {
        uint32_t a[2][4];
        ldsm_x4(Asb + a_off + ks * 32, a[0]);
        ldsm_x4(Asb + a_off + 2304 + ks * 32, a[1]);
        #pragma unroll
        for (int jj = 0; jj < 4; jj++) {
            uint32_t b[4];
            ldsm_x4t(Bsb + b_off + jj * 2304 + ks * 32, b);
            mma16816(acc[0][2 * jj + 0], a[0], b[0], b[1]);
            mma16816(acc[0][2 * jj + 1], a[0], b[2], b[3]);
            mma16816(acc[1][2 * jj + 0], a[1], b[0], b[1]);
            mma16816(acc[1][2 * jj + 1], a[1], b[2], b[3]);
        }
    }

    #pragma unroll
    for (int mi = 0; mi < 2; mi++) {
        #pragma unroll
        for (int rh = 0; rh < 2; rh++) {
            int m = m_base + mi * 16 + rh * 8 + grp;
            if (m >= 160) continue;
            int side = m / 80, rr = m % 80;
            int slot = (rr < 48) ? rr : (rr < 64 ? 96 + (rr - 48) : 128 + (rr - 64));
            float bias = g_B1[side][rr];
            __nv_bfloat16* dst = &g_Fb[side][n][slot][0];
            #pragma unroll
            for (int nj = 0; nj < 8; nj++) {
                int p = p0 + n_base + nj * 8 + tig * 2;
                if (p < Pp) {
                    __nv_bfloat162 hv = __floats2bfloat162_rn(
                        acc[mi][nj][rh * 2 + 0] + bias,
                        acc[mi][nj][rh * 2 + 1] + bias);
                    *(__nv_bfloat162*)(dst + p) = hv;
                }
            }
        }
    }
}

// ---------------- conv9 via HMMA: PERSISTENT, A staged once per CTA ----------------
#define C9_SMEM (1152 * 144 + 328 * 144)
#define C9_TILES (59 * 64)
__global__ void conv9_hmma_kernel() {
    extern __shared__ __align__(16) char smem[];
    char* As = smem;
    char* Bs = smem + 1152 * 144;
    int tid = threadIdx.x;
    int wid = tid >> 5, lane = tid & 31;
    int g8 = lane >> 3, r8 = lane & 7;
    int grp = lane >> 2, tig = lane & 3;
    int m_base = (wid & 3) * 32;
    int n_base = (wid >> 2) * 64;

    uint32_t Asb = smem_u32(As);
    uint32_t Bsb = smem_u32(Bs);
    uint32_t a_off = (uint32_t)(m_base + ((g8 & 1) << 3) + r8) * 144 + ((g8 >> 1) << 4);
    uint32_t b_off = (uint32_t)(n_base + ((g8 & 2) << 2) + r8) * 144 + ((g8 & 1) << 4);

    const uint4* wsrc = &g_W9h4[0][0][0];
    for (int i = tid; i < 9216; i += 256) {
        int row = i >> 3, ch = i & 7;
        *(uint4*)(As + row * 144 + ch * 16) = wsrc[i];
    }

    for (int t = blockIdx.x; t < C9_TILES; t += gridDim.x) {
        int px = t % 59, n = t / 59;
        int p0 = px * 128;
        __syncthreads();
        const uint4* xh = &g_xTh4[n][0][0];
        for (int i = tid; i < 2624; i += 256) {
            int row = i >> 3, ch = i & 7;
            int p = p0 - 100 + row;
            uint4 v = (p >= 0 && p < Pp) ? xh[(size_t)p * 8 + ch] : make_uint4(0, 0, 0, 0);
            *(uint4*)(Bs + row * 144 + ch * 16) = v;
        }
        __syncthreads();

        float acc[2][8][4];
        #pragma unroll
        for (int mi = 0; mi < 2; mi++)
            #pragma unroll
            for (int nj = 0; nj < 8; nj++)
                #pragma unroll
                for (int e = 0; e < 4; e++) acc[mi][nj][e] = 0.f;

        for (int tap = 0; tap < 9; tap++) {
            uint32_t abase = Asb + tap * 18432 + a_off;
            uint32_t bbase = Bsb + tap * 3600 + b_off;
            #pragma unroll
            for (int ks = 0; ks < 4; ks++) {
                uint32_t a[2][4];
                ldsm_x4(abase + ks * 32, a[0]);
                ldsm_x4(abase + 2304 + ks * 32, a[1]);
                #pragma unroll
                for (int jj = 0; jj < 4; jj++) {
                    uint32_t b[4];
                    ldsm_x4t(bbase + jj * 2304 + ks * 32, b);
                    mma16816(acc[0][2 * jj + 0], a[0], b[0], b[1]);
                    mma16816(acc[0][2 * jj + 1], a[0], b[2], b[3]);
                    mma16816(acc[1][2 * jj + 0], a[1], b[0], b[1]);
                    mma16816(acc[1][2 * jj + 1], a[1], b[2], b[3]);
                }
            }
        }

        #pragma unroll
        for (int mi = 0; mi < 2; mi++) {
            #pragma unroll
            for (int rh = 0; rh < 2; rh++) {
                int m = m_base + mi * 16 + rh * 8 + grp;
                int side = m >> 6, rr = m & 63;
                int slot = (rr < 48) ? 48 + rr : 112 + (rr - 48);
                float bias = g_B9[side][rr];
                __nv_bfloat16* dst = &g_Fb[side][n][slot][0];
                #pragma unroll
                for (int nj = 0; nj < 8; nj++) {
                    int p = p0 + n_base + nj * 8 + tig * 2;
                    if (p < Pp) {
                        __nv_bfloat162 hv = __floats2bfloat162_rn(
                            acc[mi][nj][rh * 2 + 0] + bias,
                            acc[mi][nj][rh * 2 + 1] + bias);
                        *(__nv_bfloat162*)(dst + p) = hv;
                    }
                }
            }
        }
    }
}

// ---------------- gram via HMMA + fused softmax (paired staging loads) ----------------
#define GSTR 24
__global__ void gram_hmma_kernel() {
    __shared__ __align__(16) __nv_bfloat16 f1s[4][32 * GSTR];
    __shared__ __align__(16) __nv_bfloat16 f2s[4][32 * GSTR];
    __shared__ float Msw[4][32 * 32];
    __shared__ float Mt[32 * 32];
    __shared__ float cmax[25], csum[25];

    int a_id = blockIdx.x;
    int n = blockIdx.y;
    int i = a_id / 3, g = a_id % 3;
    int slot0 = (g == 0) ? i * 16 : (g == 1 ? 48 + i * 16 : 96 + i * 16);

    int tid = threadIdx.x;
    int wid = tid >> 5, lane = tid & 31;
    int g8 = lane >> 3, r8 = lane & 7;
    int grp = lane >> 2, tig = lane & 3;

    for (int idx = tid; idx < 4 * 32 * GSTR / 2; idx += 128) {
        ((uint32_t*)f1s)[idx] = 0;
        ((uint32_t*)f2s)[idx] = 0;
    }
    __syncthreads();

    uint32_t f1b = smem_u32(&f1s[wid][0]);
    uint32_t f2b = smem_u32(&f2s[wid][0]);
    uint32_t a_off = (uint32_t)(((g8 & 1) << 3) + r8) * 48 + ((g8 >> 1) << 4);
    uint32_t b_off = (uint32_t)(((g8 & 2) << 2) + r8) * 48 + ((g8 & 1) << 4);

    float acc[2][4][4];
    #pragma unroll
    for (int mi = 0; mi < 2; mi++)
        #pragma unroll
        for (int nj = 0; nj < 4; nj++)
            #pragma unroll
            for (int e = 0; e < 4; e++) acc[mi][nj][e] = 0.f;

    for (int icl = 0; icl < 4; icl++) {
        int ic = wid * 4 + icl;
        const __nv_bfloat16* src1 = &g_Fb[0][n][slot0 + ic][0];
        const __nv_bfloat16* src2 = &g_Fb[1][n][slot0 + ic][0];
        for (int chunk = 0; chunk < 19; chunk++) {
            int t0 = chunk * 16;
            int elems = (300 - t0 >= 16) ? 400 : (300 - t0) * 25;   // always even
            int base = t0 * 25;                                     // even
            __syncwarp();
            // paired loads: 200 uint32 (4B-aligned: base & rows even)
            for (int pr = lane; pr < 200; pr += 32) {
                int idx0 = pr * 2;
                uint32_t w1 = 0, w2 = 0;
                if (idx0 < elems) {
                    w1 = *(const uint32_t*)(src1 + base + idx0);
                    w2 = *(const uint32_t*)(src2 + base + idx0);
                }
                int tt0 = idx0 / 25, u0 = idx0 % 25;
                int idx1 = idx0 + 1;
                int tt1 = idx1 / 25, u1 = idx1 % 25;
                *(uint16_t*)&f1s[wid][u0 * GSTR + tt0] = (uint16_t)(w1 & 0xffff);
                *(uint16_t*)&f1s[wid][u1 * GSTR + tt1] = (uint16_t)(w1 >> 16);
                *(uint16_t*)&f2s[wid][u0 * GSTR + tt0] = (uint16_t)(w2 & 0xffff);
                *(uint16_t*)&f2s[wid][u1 * GSTR + tt1] = (uint16_t)(w2 >> 16);
            }
            __syncwarp();
            uint32_t a[2][4];
            ldsm_x4(f1b + a_off, a[0]);
            ldsm_x4(f1b + a_off + 16 * 48, a[1]);
            #pragma unroll
            for (int nj2 = 0; nj2 < 2; nj2++) {
                uint32_t b[4];
                ldsm_x4t(f2b + b_off + nj2 * 16 * 48, b);
                mma16816(acc[0][2 * nj2 + 0], a[0], b[0], b[1]);
                mma16816(acc[0][2 * nj2 + 1], a[0], b[2], b[3]);
                mma16816(acc[1][2 * nj2 + 0], a[1], b[0], b[1]);
                mma16816(acc[1][2 * nj2 + 1], a[1], b[2], b[3]);
            }
        }
    }

    #pragma unroll
    for (int mi = 0; mi < 2; mi++)
        #pragma unroll
        for (int nj = 0; nj < 4; nj++) {
            int u0 = mi * 16 + grp;
            int v0 = nj * 8 + tig * 2;
            Msw[wid][u0 * 32 + v0]       = acc[mi][nj][0];
            Msw[wid][u0 * 32 + v0 + 1]   = acc[mi][nj][1];
            Msw[wid][(u0 + 8) * 32 + v0]     = acc[mi][nj][2];
            Msw[wid][(u0 + 8) * 32 + v0 + 1] = acc[mi][nj][3];
        }
    __syncthreads();
    for (int cell = tid; cell < 1024; cell += 128) {
        float s = Msw[0][cell] + Msw[1][cell] + Msw[2][cell] + Msw[3][cell];
        Mt[cell] = s / 4800.f;
    }
    __syncthreads();
    if (tid < 25) {
        float m = -1e30f;
        for (int uu = 0; uu < 25; uu++) m = fmaxf(m, Mt[uu * 32 + tid]);
        float s = 0.f;
        for (int uu = 0; uu < 25; uu++) s += expf(Mt[uu * 32 + tid] - m);
        cmax[tid] = m; csum[tid] = s;
    }
    __syncthreads();
    for (int cell = tid; cell < 625; cell += 128) {
        int u = cell / 25, v = cell % 25;
        g_S[n][a_id][u][v] = expf(Mt[u * 32 + v] - cmax[v]) / csum[v];
    }
}

// ---------------- combine ----------------
__global__ void combine_kernel(const float* weights) {
    int n = blockIdx.x;
    float w5 = weights[5], w6 = weights[6], w7 = weights[7];
    float* Ain = &g_Ai[n][0][0][0];
    const float* Sn = &g_S[n][0][0][0];
    for (int idx = threadIdx.x; idx < 3 * 625; idx += blockDim.x) {
        int i = idx / 625, uv = idx % 625;
        Ain[idx] = (&g_Amix[0][0][0])[i * 625 + uv]
                 + w5 * Sn[(i * 3 + 0) * 625 + uv]
                 + w6 * Sn[(i * 3 + 1) * 625 + uv]
                 + w7 * Sn[(i * 3 + 2) * 625 + uv];
    }
}

// ---------------- z = x_flat @ Ai : x staged once, all 3 subsets per block ----------------
#define Z3_SMEM ((12800 + 1875 + 12800) * 4)
__global__ void z_kernel3(const float* __restrict__ x) {
    extern __shared__ float dyn[];
    float* xs = dyn;             // 12800
    float* As = dyn + 12800;     // 3 x 625
    float* zs = dyn + 14675;     // 12800
    int blk = blockIdx.x;
    int n = blockIdx.y;
    int tid = threadIdx.x;

    for (int idx = tid; idx < 1875; idx += 256) As[idx] = (&g_Ai[n][0][0][0])[idx];
    const float* xn = x + (size_t)n * Cc * Pp;
    int gbase = blk * 12800;
    for (int idx = tid; idx < 12800; idx += 256) {
        int gi = gbase + idx;
        xs[idx] = (gi < Cc * Pp) ? xn[gi] : 0.f;
    }
    __syncthreads();

    int r0 = tid, r1 = tid + 256;
    for (int i = 0; i < 3; i++) {
        float acc0[25], acc1[25];
        #pragma unroll
        for (int v = 0; v < 25; v++) { acc0[v] = 0.f; acc1[v] = 0.f; }
        const float* Ai = As + i * 625;
        for (int u = 0; u < 25; u++) {
            float x0 = xs[r0 * 25 + u];
            float x1 = xs[r1 * 25 + u];
            #pragma unroll
            for (int v = 0; v < 25; v++) {
                float av = Ai[u * 25 + v];
                acc0[v] += av * x0;
                acc1[v] += av * x1;
            }
        }
        #pragma unroll
        for (int v = 0; v < 25; v++) {
            zs[r0 * 25 + v] = acc0[v];
            zs[r1 * 25 + v] = acc1[v];
        }
        __syncthreads();
        float* zn = &g_z[n][i][0][0];
        for (int idx = tid; idx < 12800; idx += 256) {
            int gi = gbase + idx;
            if (gi < Cc * Pp) zn[gi] = zs[idx];
        }
        __syncthreads();
    }
}

// ---------------- dconv (fp32, known-good) ----------------
#define PTD 96
__global__ void dconv_kernel(const float* __restrict__ d_w, const float* __restrict__ d_b) {
    int p0 = blockIdx.x * PTD;
    int n = blockIdx.y;
    __shared__ float ws[Cc][32];
    __shared__ float zs[32][PTD];
    int ty = threadIdx.y, tx = threadIdx.x;
    int tid = ty * 16 + tx;
    float acc[4][6];
    #pragma unroll
    for (int rr = 0; rr < 4; rr++)
        #pragma unroll
        for (int jj = 0; jj < 6; jj++) acc[rr][jj] = 0.f;
    const float* zn = &g_z[n][0][0][0];
    for (int kc = 0; kc < 6; kc++) {
        __syncthreads();
        for (int idx = tid; idx < Cc * 32; idx += 256) {
            int o = idx / 32, k32 = idx % 32;
            int kk = kc * 32 + k32;
            int i = kk / 64, c = kk % 64;
            ws[o][k32] = d_w[(i * 64 + o) * 64 + c];
        }
        for (int idx = tid; idx < 32 * PTD; idx += 256) {
            int k32 = idx / PTD, pc = idx % PTD;
            int kk = kc * 32 + k32;
            int p = p0 + pc;
            zs[k32][pc] = (p < Pp) ? zn[(size_t)kk * Pp + p] : 0.f;
        }
        __syncthreads();
        #pragma unroll
        for (int k32 = 0; k32 < 32; k32++) {
            float wv[4];
            #pragma unroll
            for (int rr = 0; rr < 4; rr++) wv[rr] = ws[ty + 16 * rr][k32];
            #pragma unroll
            for (int jj = 0; jj < 6; jj++) {
                float zv = zs[k32][tx + 16 * jj];
                #pragma unroll
                for (int rr = 0; rr < 4; rr++) acc[rr][jj] += wv[rr] * zv;
            }
        }
    }
    #pragma unroll
    for (int rr = 0; rr < 4; rr++) {
        int o = ty + 16 * rr;
        float b = d_b[o] + d_b[64 + o] + d_b[128 + o];
        #pragma unroll
        for (int jj = 0; jj < 6; jj++) {
            int p = p0 + tx + 16 * jj;
            if (p < Pp) g_y[n][o][p] = acc[rr][jj] + b;
        }
    }
}

// ---------------- BatchNorm (vectorized stage 1) ----------------
__global__ void bnstat1_kernel() {
    int o = blockIdx.x, n = blockIdx.y;
    const float4* yr = (const float4*)&g_y[n][o][0];
    float s = 0.f, s2 = 0.f;
    for (int q = threadIdx.x; q < Pp / 4; q += 256) {
        float4 v = yr[q];
        s  += v.x + v.y + v.z + v.w;
        s2 += v.x * v.x + v.y * v.y + v.z * v.z + v.w * v.w;
    }
    __shared__ float rs[256], rs2[256];
    rs[threadIdx.x] = s; rs2[threadIdx.x] = s2;
    __syncthreads();
    for (int st = 128; st > 0; st >>= 1) {
        if (threadIdx.x < st) {
            rs[threadIdx.x] += rs[threadIdx.x + st];
            rs2[threadIdx.x] += rs2[threadIdx.x + st];
        }
        __syncthreads();
    }
    if (threadIdx.x == 0) { g_part[o][n][0] = rs[0]; g_part[o][n][1] = rs2[0]; }
}

__global__ void bnstat2_kernel(const float* bn_w, const float* bn_b) {
    int o = blockIdx.x;
    __shared__ float rs[64], rs2[64];
    rs[threadIdx.x]  = g_part[o][threadIdx.x][0];
    rs2[threadIdx.x] = g_part[o][threadIdx.x][1];
    __syncthreads();
    for (int st = 32; st > 0; st >>= 1) {
        if (threadIdx.x < st) {
            rs[threadIdx.x] += rs[threadIdx.x + st];
            rs2[threadIdx.x] += rs2[threadIdx.x + st];
        }
        __syncthreads();
    }
    if (threadIdx.x == 0) {
        float M = (float)Nn * (float)Pp;
        float mu = rs[0] / M;
        float var = rs2[0] / M - mu * mu;
        float scale = bn_w[o] * rsqrtf(var + 1e-5f);
        g_bn[o][0] = scale;
        g_bn[o][1] = bn_b[o] - mu * scale;
    }
}

__global__ void final_kernel(const float* __restrict__ x, float* __restrict__ out) {
    size_t idx = (size_t)blockIdx.x * blockDim.x + threadIdx.x;   // float4 index
    size_t total4 = (size_t)Nn * Cc * Pp / 4;
    if (idx >= total4) return;
    int c = (int)((idx * 4 / Pp) % Cc);
    float sc = g_bn[c][0], sh = g_bn[c][1];
    float4 yv = ((const float4*)&g_y[0][0][0])[idx];
    float4 xv = ((const float4*)x)[idx];
    float4 r;
    r.x = fmaxf(yv.x * sc + sh + xv.x, 0.f);
    r.y = fmaxf(yv.y * sc + sh + xv.y, 0.f);
    r.z = fmaxf(yv.z * sc + sh + xv.z, 0.f);
    r.w = fmaxf(yv.w * sc + sh + xv.w, 0.f);
    ((float4*)out)[idx] = r;
}

// ---------------- launch ----------------
extern "C" void kernel_launch(void* const* d_in, const int* in_sizes, int n_in,
                              void* d_out, int out_size) {
    const float* x        = (const float*)d_in[0];
    const float* weights  = (const float*)d_in[1];
    const float* A        = (const float*)d_in[2];
    const float* a_w      = (const float*)d_in[3];
    const float* a_b      = (const float*)d_in[4];
    const float* b_w      = (const float*)d_in[5];
    const float* b_b      = (const float*)d_in[6];
    const float* d_w      = (const float*)d_in[7];
    const float* d_b      = (const float*)d_in[8];
    const float* t1_w     = (const float*)d_in[9];
    const float* t1_b     = (const float*)d_in[10];
    const float* t2_w     = (const float*)d_in[11];
    const float* t2_b     = (const float*)d_in[12];
    const float* st11_w1x1= (const float*)d_in[13];
    const float* st11_w9  = (const float*)d_in[14];
    const float* st11_b   = (const float*)d_in[15];
    const float* st12_w1x1= (const float*)d_in[16];
    const float* st12_w9  = (const float*)d_in[17];
    const float* st12_b   = (const float*)d_in[18];
    const float* bn_w     = (const float*)d_in[19];
    const float* bn_b     = (const float*)d_in[20];
    float* out = (float*)d_out;

    cudaFuncSetAttribute(z_kernel3, cudaFuncAttributeMaxDynamicSharedMemorySize, Z3_SMEM);
    cudaFuncSetAttribute(conv9_hmma_kernel, cudaFuncAttributeMaxDynamicSharedMemorySize, C9_SMEM);

    pack_kernel<<<64, 256>>>(a_w, a_b, b_w, b_b, t1_b, t2_b,
                             st11_w1x1, st11_b, st12_w1x1, st12_b);
    w9pack_kernel<<<(9 * 128 * 64 + 255) / 256, 256>>>(t1_w, t2_w, st11_w9, st12_w9);
    w1bpack_kernel<<<(192 * 64 + 255) / 256, 256>>>();
    xsplit_kernel<<<dim3(118, 64), 256>>>(x);
    amix_kernel<<<3, 625>>>(A, weights);
    conv1x1_hmma_kernel<<<dim3(59, 64), 384>>>();
    conv9_hmma_kernel<<<148, 256, C9_SMEM>>>();
    gram_hmma_kernel<<<dim3(9, 64), 128>>>();
    combine_kernel<<<64, 1024>>>(weights);
    z_kernel3<<<dim3(38, 64), 256, Z3_SMEM>>>(x);
    dconv_kernel<<<dim3(79, 64), dim3(16, 16)>>>(d_w, d_b);
    bnstat1_kernel<<<dim3(64, 64), 256>>>();
    bnstat2_kernel<<<64, 64>>>(bn_w, bn_b);
    final_kernel<<<(Nn * Cc * Pp / 4 + 255) / 256, 256>>>(x, out);
}

// round 14
// speedup vs baseline: 1.0162x; 1.0162x over previous
#include <cuda_runtime.h>
#include <cuda_bf16.h>
#include <cstdint>

#define Nn 64
#define Cc 64
#define Tt 300
#define Vv 25
#define ICn 16
#define Pp 7500      // T*V
#define SLOTS 144
#define ROWS1 80
#define ROWS9 64

// ---------------- device scratch (static; no allocations) ----------------
__device__ __nv_bfloat16 g_Fb[2][Nn][SLOTS][Pp];   // features (bf16), both sides
__device__ float g_z[Nn][3][Cc][Pp];
__device__ float g_y[Nn][Cc][Pp];
__device__ float g_S[Nn][9][Vv][Vv];
__device__ float g_Ai[Nn][3][Vv][Vv];
__device__ float g_Amix[3][Vv][Vv];
__device__ float g_W1[2][ROWS1][Cc];
__device__ float g_B1[2][ROWS1];
__device__ float g_B9[2][ROWS9];
__device__ float g_part[Cc][Nn][2];
__device__ float g_bn[Cc][2];

// bf16 data for HMMA kernels
__device__ uint4 g_W9h4[9][128][8];     // [tap][row(side*64+r)][64 bf16 channels]
__device__ uint4 g_W1b4[192][8];        // packed 1x1 weights, rows 0..159 real
__device__ uint4 g_xTh4[Nn][Pp][8];     // transposed x: [n][p][64 c] bf16

// ================= helpers =================
__device__ __forceinline__ uint32_t smem_u32(const void* p) {
    uint32_t a;
    asm("{ .reg .u64 t; cvta.to.shared.u64 t, %1; cvt.u32.u64 %0, t; }" : "=r"(a) : "l"(p));
    return a;
}

__device__ __forceinline__ void ldsm_x4(uint32_t addr, uint32_t* r) {
    asm volatile("ldmatrix.sync.aligned.m8n8.x4.shared.b16 {%0,%1,%2,%3}, [%4];"
        : "=r"(r[0]), "=r"(r[1]), "=r"(r[2]), "=r"(r[3]) : "r"(addr));
}
__device__ __forceinline__ void ldsm_x4t(uint32_t addr, uint32_t* r) {
    asm volatile("ldmatrix.sync.aligned.m8n8.x4.trans.shared.b16 {%0,%1,%2,%3}, [%4];"
        : "=r"(r[0]), "=r"(r[1]), "=r"(r[2]), "=r"(r[3]) : "r"(addr));
}
__device__ __forceinline__ void mma16816(float* d, const uint32_t* a, uint32_t b0, uint32_t b1) {
    asm volatile("mma.sync.aligned.m16n8k16.row.col.f32.bf16.bf16.f32 "
        "{%0,%1,%2,%3}, {%4,%5,%6,%7}, {%8,%9}, {%0,%1,%2,%3};"
        : "+f"(d[0]), "+f"(d[1]), "+f"(d[2]), "+f"(d[3])
        : "r"(a[0]), "r"(a[1]), "r"(a[2]), "r"(a[3]), "r"(b0), "r"(b1));
}

// ---------------- weight packing (fp32 parts) ----------------
__global__ void pack_kernel(const float* a_w, const float* a_b,
                            const float* b_w, const float* b_b,
                            const float* t1_b, const float* t2_b,
                            const float* st11_w1x1, const float* st11_b,
                            const float* st12_w1x1, const float* st12_b) {
    int tid = blockIdx.x * blockDim.x + threadIdx.x;
    int stride = gridDim.x * blockDim.x;
    for (int idx = tid; idx < 2 * ROWS1 * Cc; idx += stride) {
        int side = idx / (ROWS1 * Cc);
        int r = (idx / Cc) % ROWS1;
        int c = idx % Cc;
        const float* wab = side ? b_w : a_w;
        const float* wst = side ? st12_w1x1 : st11_w1x1;
        float v;
        if (r < 48)       v = wab[r * Cc + c];
        else if (r < 64)  v = wst[(0 * ICn + (r - 48)) * Cc + c];
        else              v = wst[(1 * ICn + (r - 64)) * Cc + c];
        g_W1[side][r][c] = v;
    }
    for (int idx = tid; idx < 2 * ROWS1; idx += stride) {
        int side = idx / ROWS1; int r = idx % ROWS1;
        const float* bab = side ? b_b : a_b;
        const float* bst = side ? st12_b : st11_b;
        float v;
        if (r < 48)       v = bab[r];
        else if (r < 64)  v = bst[0 * ICn + (r - 48)];
        else              v = bst[2 * ICn + (r - 64)];
        g_B1[side][r] = v;
    }
    for (int idx = tid; idx < 2 * ROWS9; idx += stride) {
        int side = idx / ROWS9; int r = idx % ROWS9;
        const float* bt = side ? t2_b : t1_b;
        const float* bst = side ? st12_b : st11_b;
        g_B9[side][r] = (r < 48) ? bt[r] : bst[1 * ICn + (r - 48)];
    }
}

// ---------------- W9 bf16 pack, tap-major ----------------
__global__ void w9pack_kernel(const float* t1_w, const float* t2_w,
                              const float* st11_w9, const float* st12_w9) {
    int idx = blockIdx.x * 256 + threadIdx.x;
    if (idx >= 9 * 128 * 64) return;
    int k = idx / (128 * 64);
    int r = (idx / 64) % 128;
    int c = idx % 64;
    int side = r >> 6, rr = r & 63;
    const float* wt = side ? t2_w : t1_w;
    const float* wstc = side ? st12_w9 : st11_w9;
    float w = (rr < 48) ? wt[(rr * 64 + c) * 9 + k] : wstc[((rr - 48) * 64 + c) * 9 + k];
    ((__nv_bfloat16*)g_W9h4)[(k * 128 + r) * 64 + c] = __float2bfloat16_rn(w);
}

// ---------------- W1 bf16 pack ----------------
__global__ void w1bpack_kernel() {
    int idx = blockIdx.x * 256 + threadIdx.x;
    if (idx >= 192 * 64) return;
    int r = idx / 64, c = idx % 64;
    float v = 0.f;
    if (r < 160) {
        int side = r / 80, rr = r % 80;
        v = g_W1[side][rr][c];
    }
    ((__nv_bfloat16*)g_W1b4)[r * 64 + c] = __float2bfloat16_rn(v);
}

// ---------------- x transpose + bf16 (vectorized stores) ----------------
__global__ void xsplit_kernel(const float* __restrict__ x) {
    __shared__ float s[64][65];
    int p0 = blockIdx.x * 64;
    int n = blockIdx.y;
    int tid = threadIdx.x;
    for (int i = tid; i < 4096; i += 256) {
        int c = i >> 6, j = i & 63;
        int p = p0 + j;
        s[c][j] = (p < Pp) ? x[((size_t)n * 64 + c) * Pp + p] : 0.f;
    }
    __syncthreads();
    __nv_bfloat162* oh2 = (__nv_bfloat162*)g_xTh4;
    for (int i = tid; i < 2048; i += 256) {
        int j = i >> 5, ch = i & 31;   // ch = c/2
        int p = p0 + j;
        if (p < Pp) {
            int c = ch * 2;
            __nv_bfloat162 v = __floats2bfloat162_rn(s[c][j], s[c + 1][j]);
            oh2[((size_t)n * Pp + p) * 32 + ch] = v;
        }
    }
}

// ---------------- A_mix ----------------
__global__ void amix_kernel(const float* A, const float* weights) {
    int i = blockIdx.x;
    int tid = threadIdx.x;
    int u = tid / 25, v = tid % 25;
    __shared__ float ch4sm[25][25];
    __shared__ float colmax[25], colsum[25];
    float a = A[i * 625 + tid];
    float a2 = a * a, a3 = a2 * a, a4 = a2 * a2;
    float eye = (u == v) ? 1.f : 0.f;
    float ch4 = 8.f * a4 - 8.f * a2 + eye;
    float ch3 = 4.f * a3 - 3.f * a;
    float ch2 = 2.f * a2 - eye;
    ch4sm[u][v] = ch4 / 25.f;
    __syncthreads();
    if (tid < 25) {
        float m = -1e30f;
        for (int uu = 0; uu < 25; uu++) m = fmaxf(m, ch4sm[uu][tid]);
        float s = 0.f;
        for (int uu = 0; uu < 25; uu++) s += expf(ch4sm[uu][tid] - m);
        colmax[tid] = m; colsum[tid] = s;
    }
    __syncthreads();
    float ch4s = expf(ch4 / 25.f - colmax[v]) / colsum[v];
    g_Amix[i][u][v] = weights[0] * a + weights[1] * ch4s + weights[2] * ch4
                    + weights[3] * ch3 + weights[4] * ch2;
}

// ---------------- conv1x1 via HMMA ----------------
__global__ void conv1x1_hmma_kernel() {
    __shared__ __align__(16) __nv_bfloat16 As[192 * 72];
    __shared__ __align__(16) __nv_bfloat16 Bs[128 * 72];
    int p0 = blockIdx.x * 128;
    int n = blockIdx.y;
    int tid = threadIdx.x;
    int wid = tid >> 5, lane = tid & 31;
    int g8 = lane >> 3, r8 = lane & 7;
    int grp = lane >> 2, tig = lane & 3;
    int m_base = (wid % 6) * 32;
    int n_base = (wid / 6) * 64;

    uint32_t Asb = smem_u32(As);
    uint32_t Bsb = smem_u32(Bs);
    uint32_t a_off = (uint32_t)(m_base + ((g8 & 1) << 3) + r8) * 144 + ((g8 >> 1) << 4);
    uint32_t b_off = (uint32_t)(n_base + ((g8 & 2) << 2) + r8) * 144 + ((g8 & 1) << 4);

    const uint4* xh = &g_xTh4[n][0][0];
    for (int i = tid; i < 1536; i += 384) {
        int row = i >> 3, ch = i & 7;
        *(uint4*)((char*)As + row * 144 + ch * 16) = g_W1b4[row][ch];
    }
    for (int i = tid; i < 1024; i += 384) {
        int row = i >> 3, ch = i & 7;
        int p = p0 + row;
        uint4 v = (p < Pp) ? xh[(size_t)p * 8 + ch] : make_uint4(0, 0, 0, 0);
        *(uint4*)((char*)Bs + row * 144 + ch * 16) = v;
    }
    __syncthreads();

    float acc[2][8][4];
    #pragma unroll
    for (int mi = 0; mi < 2; mi++)
        #pragma unroll
        for (int nj = 0; nj < 8; nj++)
            #pragma unroll
            for (int e = 0; e < 4; e++) acc[mi][nj][e] = 0.f;

    #pragma unroll
    for (int ks = 0; ks < 4; ks++) {
        uint32_t a[2][4];
        ldsm_x4(Asb + a_off + ks * 32, a[0]);
        ldsm_x4(Asb + a_off + 2304 + ks * 32, a[1]);
        #pragma unroll
        for (int jj = 0; jj < 4; jj++) {
            uint32_t b[4];
            ldsm_x4t(Bsb + b_off + jj * 2304 + ks * 32, b);
            mma16816(acc[0][2 * jj + 0], a[0], b[0], b[1]);
            mma16816(acc[0][2 * jj + 1], a[0], b[2], b[3]);
            mma16816(acc[1][2 * jj + 0], a[1], b[0], b[1]);
            mma16816(acc[1][2 * jj + 1], a[1], b[2], b[3]);
        }
    }

    #pragma unroll
    for (int mi = 0; mi < 2; mi++) {
        #pragma unroll
        for (int rh = 0; rh < 2; rh++) {
            int m = m_base + mi * 16 + rh * 8 + grp;
            if (m >= 160) continue;
            int side = m / 80, rr = m % 80;
            int slot = (rr < 48) ? rr : (rr < 64 ? 96 + (rr - 48) : 128 + (rr - 64));
            float bias = g_B1[side][rr];
            __nv_bfloat16* dst = &g_Fb[side][n][slot][0];
            #pragma unroll
            for (int nj = 0; nj < 8; nj++) {
                int p = p0 + n_base + nj * 8 + tig * 2;
                if (p < Pp) {
                    __nv_bfloat162 hv = __floats2bfloat162_rn(
                        acc[mi][nj][rh * 2 + 0] + bias,
                        acc[mi][nj][rh * 2 + 1] + bias);
                    *(__nv_bfloat162*)(dst + p) = hv;
                }
            }
        }
    }
}

// ---------------- conv9 via HMMA: PERSISTENT, A staged once per CTA ----------------
#define C9_SMEM (1152 * 144 + 328 * 144)
#define C9_TILES (59 * 64)
__global__ void conv9_hmma_kernel() {
    extern __shared__ __align__(16) char smem[];
    char* As = smem;
    char* Bs = smem + 1152 * 144;
    int tid = threadIdx.x;
    int wid = tid >> 5, lane = tid & 31;
    int g8 = lane >> 3, r8 = lane & 7;
    int grp = lane >> 2, tig = lane & 3;
    int m_base = (wid & 3) * 32;
    int n_base = (wid >> 2) * 64;

    uint32_t Asb = smem_u32(As);
    uint32_t Bsb = smem_u32(Bs);
    uint32_t a_off = (uint32_t)(m_base + ((g8 & 1) << 3) + r8) * 144 + ((g8 >> 1) << 4);
    uint32_t b_off = (uint32_t)(n_base + ((g8 & 2) << 2) + r8) * 144 + ((g8 & 1) << 4);

    const uint4* wsrc = &g_W9h4[0][0][0];
    for (int i = tid; i < 9216; i += 256) {
        int row = i >> 3, ch = i & 7;
        *(uint4*)(As + row * 144 + ch * 16) = wsrc[i];
    }

    for (int t = blockIdx.x; t < C9_TILES; t += gridDim.x) {
        int px = t % 59, n = t / 59;
        int p0 = px * 128;
        __syncthreads();
        const uint4* xh = &g_xTh4[n][0][0];
        for (int i = tid; i < 2624; i += 256) {
            int row = i >> 3, ch = i & 7;
            int p = p0 - 100 + row;
            uint4 v = (p >= 0 && p < Pp) ? xh[(size_t)p * 8 + ch] : make_uint4(0, 0, 0, 0);
            *(uint4*)(Bs + row * 144 + ch * 16) = v;
        }
        __syncthreads();

        float acc[2][8][4];
        #pragma unroll
        for (int mi = 0; mi < 2; mi++)
            #pragma unroll
            for (int nj = 0; nj < 8; nj++)
                #pragma unroll
                for (int e = 0; e < 4; e++) acc[mi][nj][e] = 0.f;

        for (int tap = 0; tap < 9; tap++) {
            uint32_t abase = Asb + tap * 18432 + a_off;
            uint32_t bbase = Bsb + tap * 3600 + b_off;
            #pragma unroll
            for (int ks = 0; ks < 4; ks++) {
                uint32_t a[2][4];
                ldsm_x4(abase + ks * 32, a[0]);
                ldsm_x4(abase + 2304 + ks * 32, a[1]);
                #pragma unroll
                for (int jj = 0; jj < 4; jj++) {
                    uint32_t b[4];
                    ldsm_x4t(bbase + jj * 2304 + ks * 32, b);
                    mma16816(acc[0][2 * jj + 0], a[0], b[0], b[1]);
                    mma16816(acc[0][2 * jj + 1], a[0], b[2], b[3]);
                    mma16816(acc[1][2 * jj + 0], a[1], b[0], b[1]);
                    mma16816(acc[1][2 * jj + 1], a[1], b[2], b[3]);
                }
            }
        }

        #pragma unroll
        for (int mi = 0; mi < 2; mi++) {
            #pragma unroll
            for (int rh = 0; rh < 2; rh++) {
                int m = m_base + mi * 16 + rh * 8 + grp;
                int side = m >> 6, rr = m & 63;
                int slot = (rr < 48) ? 48 + rr : 112 + (rr - 48);
                float bias = g_B9[side][rr];
                __nv_bfloat16* dst = &g_Fb[side][n][slot][0];
                #pragma unroll
                for (int nj = 0; nj < 8; nj++) {
                    int p = p0 + n_base + nj * 8 + tig * 2;
                    if (p < Pp) {
                        __nv_bfloat162 hv = __floats2bfloat162_rn(
                            acc[mi][nj][rh * 2 + 0] + bias,
                            acc[mi][nj][rh * 2 + 1] + bias);
                        *(__nv_bfloat162*)(dst + p) = hv;
                    }
                }
            }
        }
    }
}

// ---------------- gram via HMMA, 8 warps (2 ic each) + fused softmax ----------------
#define GSTR 24
// dyn smem: f1s 8*1536 | f2s 8*1536 | Msw 8*4096 | Mt 4096 | cmax 128 | csum 128
#define G8_SMEM (12288 + 12288 + 32768 + 4096 + 256)
__global__ void gram_hmma_kernel() {
    extern __shared__ __align__(16) char gsm[];
    __nv_bfloat16* f1a = (__nv_bfloat16*)gsm;                 // [8][768]
    __nv_bfloat16* f2a = (__nv_bfloat16*)(gsm + 12288);
    float* Msw = (float*)(gsm + 24576);                        // [8][1024]
    float* Mt  = (float*)(gsm + 24576 + 32768);                // [1024]
    float* cmax = (float*)(gsm + 24576 + 32768 + 4096);        // [32]
    float* csum = cmax + 32;

    int a_id = blockIdx.x;
    int n = blockIdx.y;
    int i = a_id / 3, g = a_id % 3;
    int slot0 = (g == 0) ? i * 16 : (g == 1 ? 48 + i * 16 : 96 + i * 16);

    int tid = threadIdx.x;
    int wid = tid >> 5, lane = tid & 31;
    int g8 = lane >> 3, r8 = lane & 7;
    int grp = lane >> 2, tig = lane & 3;

    // zero both staging regions (pad cells stay zero)
    for (int idx = tid; idx < 6144; idx += 256)
        ((uint32_t*)gsm)[idx] = 0;
    __syncthreads();

    __nv_bfloat16* f1s = f1a + wid * 768;
    __nv_bfloat16* f2s = f2a + wid * 768;
    uint32_t f1b = smem_u32(f1s);
    uint32_t f2b = smem_u32(f2s);
    uint32_t a_off = (uint32_t)(((g8 & 1) << 3) + r8) * 48 + ((g8 >> 1) << 4);
    uint32_t b_off = (uint32_t)(((g8 & 2) << 2) + r8) * 48 + ((g8 & 1) << 4);

    float acc[2][4][4];
    #pragma unroll
    for (int mi = 0; mi < 2; mi++)
        #pragma unroll
        for (int nj = 0; nj < 4; nj++)
            #pragma unroll
            for (int e = 0; e < 4; e++) acc[mi][nj][e] = 0.f;

    const __nv_bfloat16 z16 = __float2bfloat16_rn(0.f);
    for (int icl = 0; icl < 2; icl++) {
        int ic = wid * 2 + icl;
        const __nv_bfloat16* src1 = &g_Fb[0][n][slot0 + ic][0];
        const __nv_bfloat16* src2 = &g_Fb[1][n][slot0 + ic][0];
        for (int chunk = 0; chunk < 19; chunk++) {
            int t0 = chunk * 16;
            int elems = (300 - t0 >= 16) ? 400 : (300 - t0) * 25;
            int base = t0 * 25;
            __syncwarp();
            for (int idx = lane; idx < 400; idx += 32) {
                __nv_bfloat16 v1 = (idx < elems) ? src1[base + idx] : z16;
                __nv_bfloat16 v2 = (idx < elems) ? src2[base + idx] : z16;
                int tt = idx / 25, u = idx % 25;
                f1s[u * GSTR + tt] = v1;
                f2s[u * GSTR + tt] = v2;
            }
            __syncwarp();
            uint32_t a[2][4];
            ldsm_x4(f1b + a_off, a[0]);
            ldsm_x4(f1b + a_off + 16 * 48, a[1]);
            #pragma unroll
            for (int nj2 = 0; nj2 < 2; nj2++) {
                uint32_t b[4];
                ldsm_x4t(f2b + b_off + nj2 * 16 * 48, b);
                mma16816(acc[0][2 * nj2 + 0], a[0], b[0], b[1]);
                mma16816(acc[0][2 * nj2 + 1], a[0], b[2], b[3]);
                mma16816(acc[1][2 * nj2 + 0], a[1], b[0], b[1]);
                mma16816(acc[1][2 * nj2 + 1], a[1], b[2], b[3]);
            }
        }
    }

    float* Mw = Msw + wid * 1024;
    #pragma unroll
    for (int mi = 0; mi < 2; mi++)
        #pragma unroll
        for (int nj = 0; nj < 4; nj++) {
            int u0 = mi * 16 + grp;
            int v0 = nj * 8 + tig * 2;
            Mw[u0 * 32 + v0]           = acc[mi][nj][0];
            Mw[u0 * 32 + v0 + 1]       = acc[mi][nj][1];
            Mw[(u0 + 8) * 32 + v0]     = acc[mi][nj][2];
            Mw[(u0 + 8) * 32 + v0 + 1] = acc[mi][nj][3];
        }
    __syncthreads();
    for (int cell = tid; cell < 1024; cell += 256) {
        float s = 0.f;
        #pragma unroll
        for (int w = 0; w < 8; w++) s += Msw[w * 1024 + cell];
        Mt[cell] = s / 4800.f;
    }
    __syncthreads();
    if (tid < 25) {
        float m = -1e30f;
        for (int uu = 0; uu < 25; uu++) m = fmaxf(m, Mt[uu * 32 + tid]);
        float s = 0.f;
        for (int uu = 0; uu < 25; uu++) s += expf(Mt[uu * 32 + tid] - m);
        cmax[tid] = m; csum[tid] = s;
    }
    __syncthreads();
    for (int cell = tid; cell < 625; cell += 256) {
        int u = cell / 25, v = cell % 25;
        g_S[n][a_id][u][v] = expf(Mt[u * 32 + v] - cmax[v]) / csum[v];
    }
}

// ---------------- combine ----------------
__global__ void combine_kernel(const float* weights) {
    int n = blockIdx.x;
    float w5 = weights[5], w6 = weights[6], w7 = weights[7];
    float* Ain = &g_Ai[n][0][0][0];
    const float* Sn = &g_S[n][0][0][0];
    for (int idx = threadIdx.x; idx < 3 * 625; idx += blockDim.x) {
        int i = idx / 625, uv = idx % 625;
        Ain[idx] = (&g_Amix[0][0][0])[i * 625 + uv]
                 + w5 * Sn[(i * 3 + 0) * 625 + uv]
                 + w6 * Sn[(i * 3 + 1) * 625 + uv]
                 + w7 * Sn[(i * 3 + 2) * 625 + uv];
    }
}

// ---------------- z = x_flat @ Ai : x staged once, all 3 subsets per block ----------------
#define Z3_SMEM ((12800 + 1875 + 12800) * 4)
__global__ void z_kernel3(const float* __restrict__ x) {
    extern __shared__ float dyn[];
    float* xs = dyn;             // 12800
    float* As = dyn + 12800;     // 3 x 625
    float* zs = dyn + 14675;     // 12800
    int blk = blockIdx.x;
    int n = blockIdx.y;
    int tid = threadIdx.x;

    for (int idx = tid; idx < 1875; idx += 256) As[idx] = (&g_Ai[n][0][0][0])[idx];
    const float* xn = x + (size_t)n * Cc * Pp;
    int gbase = blk * 12800;
    for (int idx = tid; idx < 12800; idx += 256) {
        int gi = gbase + idx;
        xs[idx] = (gi < Cc * Pp) ? xn[gi] : 0.f;
    }
    __syncthreads();

    int r0 = tid, r1 = tid + 256;
    for (int i = 0; i < 3; i++) {
        float acc0[25], acc1[25];
        #pragma unroll
        for (int v = 0; v < 25; v++) { acc0[v] = 0.f; acc1[v] = 0.f; }
        const float* Ai = As + i * 625;
        for (int u = 0; u < 25; u++) {
            float x0 = xs[r0 * 25 + u];
            float x1 = xs[r1 * 25 + u];
            #pragma unroll
            for (int v = 0; v < 25; v++) {
                float av = Ai[u * 25 + v];
                acc0[v] += av * x0;
                acc1[v] += av * x1;
            }
        }
        #pragma unroll
        for (int v = 0; v < 25; v++) {
            zs[r0 * 25 + v] = acc0[v];
            zs[r1 * 25 + v] = acc1[v];
        }
        __syncthreads();
        float* zn = &g_z[n][i][0][0];
        for (int idx = tid; idx < 12800; idx += 256) {
            int gi = gbase + idx;
            if (gi < Cc * Pp) zn[gi] = zs[idx];
        }
        __syncthreads();
    }
}

// ---------------- dconv (fp32, known-good) ----------------
#define PTD 96
__global__ void dconv_kernel(const float* __restrict__ d_w, const float* __restrict__ d_b) {
    int p0 = blockIdx.x * PTD;
    int n = blockIdx.y;
    __shared__ float ws[Cc][32];
    __shared__ float zs[32][PTD];
    int ty = threadIdx.y, tx = threadIdx.x;
    int tid = ty * 16 + tx;
    float acc[4][6];
    #pragma unroll
    for (int rr = 0; rr < 4; rr++)
        #pragma unroll
        for (int jj = 0; jj < 6; jj++) acc[rr][jj] = 0.f;
    const float* zn = &g_z[n][0][0][0];
    for (int kc = 0; kc < 6; kc++) {
        __syncthreads();
        for (int idx = tid; idx < Cc * 32; idx += 256) {
            int o = idx / 32, k32 = idx % 32;
            int kk = kc * 32 + k32;
            int i = kk / 64, c = kk % 64;
            ws[o][k32] = d_w[(i * 64 + o) * 64 + c];
        }
        for (int idx = tid; idx < 32 * PTD; idx += 256) {
            int k32 = idx / PTD, pc = idx % PTD;
            int kk = kc * 32 + k32;
            int p = p0 + pc;
            zs[k32][pc] = (p < Pp) ? zn[(size_t)kk * Pp + p] : 0.f;
        }
        __syncthreads();
        #pragma unroll
        for (int k32 = 0; k32 < 32; k32++) {
            float wv[4];
            #pragma unroll
            for (int rr = 0; rr < 4; rr++) wv[rr] = ws[ty + 16 * rr][k32];
            #pragma unroll
            for (int jj = 0; jj < 6; jj++) {
                float zv = zs[k32][tx + 16 * jj];
                #pragma unroll
                for (int rr = 0; rr < 4; rr++) acc[rr][jj] += wv[rr] * zv;
            }
        }
    }
    #pragma unroll
    for (int rr = 0; rr < 4; rr++) {
        int o = ty + 16 * rr;
        float b = d_b[o] + d_b[64 + o] + d_b[128 + o];
        #pragma unroll
        for (int jj = 0; jj < 6; jj++) {
            int p = p0 + tx + 16 * jj;
            if (p < Pp) g_y[n][o][p] = acc[rr][jj] + b;
        }
    }
}

// ---------------- BatchNorm (vectorized stage 1) ----------------
__global__ void bnstat1_kernel() {
    int o = blockIdx.x, n = blockIdx.y;
    const float4* yr = (const float4*)&g_y[n][o][0];
    float s = 0.f, s2 = 0.f;
    for (int q = threadIdx.x; q < Pp / 4; q += 256) {
        float4 v = yr[q];
        s  += v.x + v.y + v.z + v.w;
        s2 += v.x * v.x + v.y * v.y + v.z * v.z + v.w * v.w;
    }
    __shared__ float rs[256], rs2[256];
    rs[threadIdx.x] = s; rs2[threadIdx.x] = s2;
    __syncthreads();
    for (int st = 128; st > 0; st >>= 1) {
        if (threadIdx.x < st) {
            rs[threadIdx.x] += rs[threadIdx.x + st];
            rs2[threadIdx.x] += rs2[threadIdx.x + st];
        }
        __syncthreads();
    }
    if (threadIdx.x == 0) { g_part[o][n][0] = rs[0]; g_part[o][n][1] = rs2[0]; }
}

__global__ void bnstat2_kernel(const float* bn_w, const float* bn_b) {
    int o = blockIdx.x;
    __shared__ float rs[64], rs2[64];
    rs[threadIdx.x]  = g_part[o][threadIdx.x][0];
    rs2[threadIdx.x] = g_part[o][threadIdx.x][1];
    __syncthreads();
    for (int st = 32; st > 0; st >>= 1) {
        if (threadIdx.x < st) {
            rs[threadIdx.x] += rs[threadIdx.x + st];
            rs2[threadIdx.x] += rs2[threadIdx.x + st];
        }
        __syncthreads();
    }
    if (threadIdx.x == 0) {
        float M = (float)Nn * (float)Pp;
        float mu = rs[0] / M;
        float var = rs2[0] / M - mu * mu;
        float scale = bn_w[o] * rsqrtf(var + 1e-5f);
        g_bn[o][0] = scale;
        g_bn[o][1] = bn_b[o] - mu * scale;
    }
}

__global__ void final_kernel(const float* __restrict__ x, float* __restrict__ out) {
    size_t idx = (size_t)blockIdx.x * blockDim.x + threadIdx.x;   // float4 index
    size_t total4 = (size_t)Nn * Cc * Pp / 4;
    if (idx >= total4) return;
    int c = (int)((idx * 4 / Pp) % Cc);
    float sc = g_bn[c][0], sh = g_bn[c][1];
    float4 yv = ((const float4*)&g_y[0][0][0])[idx];
    float4 xv = ((const float4*)x)[idx];
    float4 r;
    r.x = fmaxf(yv.x * sc + sh + xv.x, 0.f);
    r.y = fmaxf(yv.y * sc + sh + xv.y, 0.f);
    r.z = fmaxf(yv.z * sc + sh + xv.z, 0.f);
    r.w = fmaxf(yv.w * sc + sh + xv.w, 0.f);
    ((float4*)out)[idx] = r;
}

// ---------------- launch ----------------
extern "C" void kernel_launch(void* const* d_in, const int* in_sizes, int n_in,
                              void* d_out, int out_size) {
    const float* x        = (const float*)d_in[0];
    const float* weights  = (const float*)d_in[1];
    const float* A        = (const float*)d_in[2];
    const float* a_w      = (const float*)d_in[3];
    const float* a_b      = (const float*)d_in[4];
    const float* b_w      = (const float*)d_in[5];
    const float* b_b      = (const float*)d_in[6];
    const float* d_w      = (const float*)d_in[7];
    const float* d_b      = (const float*)d_in[8];
    const float* t1_w     = (const float*)d_in[9];
    const float* t1_b     = (const float*)d_in[10];
    const float* t2_w     = (const float*)d_in[11];
    const float* t2_b     = (const float*)d_in[12];
    const float* st11_w1x1= (const float*)d_in[13];
    const float* st11_w9  = (const float*)d_in[14];
    const float* st11_b   = (const float*)d_in[15];
    const float* st12_w1x1= (const float*)d_in[16];
    const float* st12_w9  = (const float*)d_in[17];
    const float* st12_b   = (const float*)d_in[18];
    const float* bn_w     = (const float*)d_in[19];
    const float* bn_b     = (const float*)d_in[20];
    float* out = (float*)d_out;

    cudaFuncSetAttribute(z_kernel3, cudaFuncAttributeMaxDynamicSharedMemorySize, Z3_SMEM);
    cudaFuncSetAttribute(conv9_hmma_kernel, cudaFuncAttributeMaxDynamicSharedMemorySize, C9_SMEM);
    cudaFuncSetAttribute(gram_hmma_kernel, cudaFuncAttributeMaxDynamicSharedMemorySize, G8_SMEM);

    pack_kernel<<<64, 256>>>(a_w, a_b, b_w, b_b, t1_b, t2_b,
                             st11_w1x1, st11_b, st12_w1x1, st12_b);
    w9pack_kernel<<<(9 * 128 * 64 + 255) / 256, 256>>>(t1_w, t2_w, st11_w9, st12_w9);
    w1bpack_kernel<<<(192 * 64 + 255) / 256, 256>>>();
    xsplit_kernel<<<dim3(118, 64), 256>>>(x);
    amix_kernel<<<3, 625>>>(A, weights);
    conv1x1_hmma_kernel<<<dim3(59, 64), 384>>>();
    conv9_hmma_kernel<<<148, 256, C9_SMEM>>>();
    gram_hmma_kernel<<<dim3(9, 64), 256, G8_SMEM>>>();
    combine_kernel<<<64, 1024>>>(weights);
    z_kernel3<<<dim3(38, 64), 256, Z3_SMEM>>>(x);
    dconv_kernel<<<dim3(79, 64), dim3(16, 16)>>>(d_w, d_b);
    bnstat1_kernel<<<dim3(64, 64), 256>>>();
    bnstat2_kernel<<<64, 64>>>(bn_w, bn_b);
    final_kernel<<<(Nn * Cc * Pp / 4 + 255) / 256, 256>>>(x, out);
}

// round 15
// speedup vs baseline: 1.0697x; 1.0527x over previous
#include <cuda_runtime.h>
#include <cuda_bf16.h>
#include <cstdint>

#define Nn 64
#define Cc 64
#define Tt 300
#define Vv 25
#define ICn 16
#define Pp 7500      // T*V
#define SLOTS 144
#define ROWS1 80
#define ROWS9 64

// ---------------- device scratch (static; no allocations) ----------------
__device__ __nv_bfloat16 g_Fb[2][Nn][SLOTS][Pp];   // features (bf16), both sides
__device__ float g_z[Nn][3][Cc][Pp];
__device__ float g_y[Nn][Cc][Pp];
__device__ float g_S[Nn][9][Vv][Vv];
__device__ float g_Ai[Nn][3][Vv][Vv];
__device__ float g_Amix[3][Vv][Vv];
__device__ float g_W1[2][ROWS1][Cc];
__device__ float g_B1[2][ROWS1];
__device__ float g_B9[2][ROWS9];
__device__ float g_part[Cc][Nn][2];
__device__ float g_bn[Cc][2];

// bf16 data for HMMA kernels
__device__ uint4 g_W9h4[9][128][8];     // [tap][row(side*64+r)][64 bf16 channels]
__device__ uint4 g_W1b4[192][8];        // packed 1x1 weights, rows 0..159 real
__device__ uint4 g_xTh4[Nn][Pp][8];     // transposed x: [n][p][64 c] bf16

// ================= helpers =================
__device__ __forceinline__ uint32_t smem_u32(const void* p) {
    uint32_t a;
    asm("{ .reg .u64 t; cvta.to.shared.u64 t, %1; cvt.u32.u64 %0, t; }" : "=r"(a) : "l"(p));
    return a;
}

__device__ __forceinline__ void ldsm_x4(uint32_t addr, uint32_t* r) {
    asm volatile("ldmatrix.sync.aligned.m8n8.x4.shared.b16 {%0,%1,%2,%3}, [%4];"
        : "=r"(r[0]), "=r"(r[1]), "=r"(r[2]), "=r"(r[3]) : "r"(addr));
}
__device__ __forceinline__ void ldsm_x4t(uint32_t addr, uint32_t* r) {
    asm volatile("ldmatrix.sync.aligned.m8n8.x4.trans.shared.b16 {%0,%1,%2,%3}, [%4];"
        : "=r"(r[0]), "=r"(r[1]), "=r"(r[2]), "=r"(r[3]) : "r"(addr));
}
__device__ __forceinline__ void mma16816(float* d, const uint32_t* a, uint32_t b0, uint32_t b1) {
    asm volatile("mma.sync.aligned.m16n8k16.row.col.f32.bf16.bf16.f32 "
        "{%0,%1,%2,%3}, {%4,%5,%6,%7}, {%8,%9}, {%0,%1,%2,%3};"
        : "+f"(d[0]), "+f"(d[1]), "+f"(d[2]), "+f"(d[3])
        : "r"(a[0]), "r"(a[1]), "r"(a[2]), "r"(a[3]), "r"(b0), "r"(b1));
}

// ---------------- weight packing (fp32 parts) ----------------
__global__ void pack_kernel(const float* a_w, const float* a_b,
                            const float* b_w, const float* b_b,
                            const float* t1_b, const float* t2_b,
                            const float* st11_w1x1, const float* st11_b,
                            const float* st12_w1x1, const float* st12_b) {
    int tid = blockIdx.x * blockDim.x + threadIdx.x;
    int stride = gridDim.x * blockDim.x;
    for (int idx = tid; idx < 2 * ROWS1 * Cc; idx += stride) {
        int side = idx / (ROWS1 * Cc);
        int r = (idx / Cc) % ROWS1;
        int c = idx % Cc;
        const float* wab = side ? b_w : a_w;
        const float* wst = side ? st12_w1x1 : st11_w1x1;
        float v;
        if (r < 48)       v = wab[r * Cc + c];
        else if (r < 64)  v = wst[(0 * ICn + (r - 48)) * Cc + c];
        else              v = wst[(1 * ICn + (r - 64)) * Cc + c];
        g_W1[side][r][c] = v;
    }
    for (int idx = tid; idx < 2 * ROWS1; idx += stride) {
        int side = idx / ROWS1; int r = idx % ROWS1;
        const float* bab = side ? b_b : a_b;
        const float* bst = side ? st12_b : st11_b;
        float v;
        if (r < 48)       v = bab[r];
        else if (r < 64)  v = bst[0 * ICn + (r - 48)];
        else              v = bst[2 * ICn + (r - 64)];
        g_B1[side][r] = v;
    }
    for (int idx = tid; idx < 2 * ROWS9; idx += stride) {
        int side = idx / ROWS9; int r = idx % ROWS9;
        const float* bt = side ? t2_b : t1_b;
        const float* bst = side ? st12_b : st11_b;
        g_B9[side][r] = (r < 48) ? bt[r] : bst[1 * ICn + (r - 48)];
    }
}

// ---------------- W9 bf16 pack, tap-major ----------------
__global__ void w9pack_kernel(const float* t1_w, const float* t2_w,
                              const float* st11_w9, const float* st12_w9) {
    int idx = blockIdx.x * 256 + threadIdx.x;
    if (idx >= 9 * 128 * 64) return;
    int k = idx / (128 * 64);
    int r = (idx / 64) % 128;
    int c = idx % 64;
    int side = r >> 6, rr = r & 63;
    const float* wt = side ? t2_w : t1_w;
    const float* wstc = side ? st12_w9 : st11_w9;
    float w = (rr < 48) ? wt[(rr * 64 + c) * 9 + k] : wstc[((rr - 48) * 64 + c) * 9 + k];
    ((__nv_bfloat16*)g_W9h4)[(k * 128 + r) * 64 + c] = __float2bfloat16_rn(w);
}

// ---------------- W1 bf16 pack ----------------
__global__ void w1bpack_kernel() {
    int idx = blockIdx.x * 256 + threadIdx.x;
    if (idx >= 192 * 64) return;
    int r = idx / 64, c = idx % 64;
    float v = 0.f;
    if (r < 160) {
        int side = r / 80, rr = r % 80;
        v = g_W1[side][rr][c];
    }
    ((__nv_bfloat16*)g_W1b4)[r * 64 + c] = __float2bfloat16_rn(v);
}

// ---------------- x transpose + bf16 (vectorized stores) ----------------
__global__ void xsplit_kernel(const float* __restrict__ x) {
    __shared__ float s[64][65];
    int p0 = blockIdx.x * 64;
    int n = blockIdx.y;
    int tid = threadIdx.x;
    for (int i = tid; i < 4096; i += 256) {
        int c = i >> 6, j = i & 63;
        int p = p0 + j;
        s[c][j] = (p < Pp) ? x[((size_t)n * 64 + c) * Pp + p] : 0.f;
    }
    __syncthreads();
    __nv_bfloat162* oh2 = (__nv_bfloat162*)g_xTh4;
    for (int i = tid; i < 2048; i += 256) {
        int j = i >> 5, ch = i & 31;   // ch = c/2
        int p = p0 + j;
        if (p < Pp) {
            int c = ch * 2;
            __nv_bfloat162 v = __floats2bfloat162_rn(s[c][j], s[c + 1][j]);
            oh2[((size_t)n * Pp + p) * 32 + ch] = v;
        }
    }
}

// ---------------- A_mix ----------------
__global__ void amix_kernel(const float* A, const float* weights) {
    int i = blockIdx.x;
    int tid = threadIdx.x;
    int u = tid / 25, v = tid % 25;
    __shared__ float ch4sm[25][25];
    __shared__ float colmax[25], colsum[25];
    float a = A[i * 625 + tid];
    float a2 = a * a, a3 = a2 * a, a4 = a2 * a2;
    float eye = (u == v) ? 1.f : 0.f;
    float ch4 = 8.f * a4 - 8.f * a2 + eye;
    float ch3 = 4.f * a3 - 3.f * a;
    float ch2 = 2.f * a2 - eye;
    ch4sm[u][v] = ch4 / 25.f;
    __syncthreads();
    if (tid < 25) {
        float m = -1e30f;
        for (int uu = 0; uu < 25; uu++) m = fmaxf(m, ch4sm[uu][tid]);
        float s = 0.f;
        for (int uu = 0; uu < 25; uu++) s += expf(ch4sm[uu][tid] - m);
        colmax[tid] = m; colsum[tid] = s;
    }
    __syncthreads();
    float ch4s = expf(ch4 / 25.f - colmax[v]) / colsum[v];
    g_Amix[i][u][v] = weights[0] * a + weights[1] * ch4s + weights[2] * ch4
                    + weights[3] * ch3 + weights[4] * ch2;
}

// ---------------- conv1x1 via HMMA ----------------
__global__ void conv1x1_hmma_kernel() {
    __shared__ __align__(16) __nv_bfloat16 As[192 * 72];
    __shared__ __align__(16) __nv_bfloat16 Bs[128 * 72];
    int p0 = blockIdx.x * 128;
    int n = blockIdx.y;
    int tid = threadIdx.x;
    int wid = tid >> 5, lane = tid & 31;
    int g8 = lane >> 3, r8 = lane & 7;
    int grp = lane >> 2, tig = lane & 3;
    int m_base = (wid % 6) * 32;
    int n_base = (wid / 6) * 64;

    uint32_t Asb = smem_u32(As);
    uint32_t Bsb = smem_u32(Bs);
    uint32_t a_off = (uint32_t)(m_base + ((g8 & 1) << 3) + r8) * 144 + ((g8 >> 1) << 4);
    uint32_t b_off = (uint32_t)(n_base + ((g8 & 2) << 2) + r8) * 144 + ((g8 & 1) << 4);

    const uint4* xh = &g_xTh4[n][0][0];
    for (int i = tid; i < 1536; i += 384) {
        int row = i >> 3, ch = i & 7;
        *(uint4*)((char*)As + row * 144 + ch * 16) = g_W1b4[row][ch];
    }
    for (int i = tid; i < 1024; i += 384) {
        int row = i >> 3, ch = i & 7;
        int p = p0 + row;
        uint4 v = (p < Pp) ? xh[(size_t)p * 8 + ch] : make_uint4(0, 0, 0, 0);
        *(uint4*)((char*)Bs + row * 144 + ch * 16) = v;
    }
    __syncthreads();

    float acc[2][8][4];
    #pragma unroll
    for (int mi = 0; mi < 2; mi++)
        #pragma unroll
        for (int nj = 0; nj < 8; nj++)
            #pragma unroll
            for (int e = 0; e < 4; e++) acc[mi][nj][e] = 0.f;

    #pragma unroll
    for (int ks = 0; ks < 4; ks++) {
        uint32_t a[2][4];
        ldsm_x4(Asb + a_off + ks * 32, a[0]);
        ldsm_x4(Asb + a_off + 2304 + ks * 32, a[1]);
        #pragma unroll
        for (int jj = 0; jj < 4; jj++) {
            uint32_t b[4];
            ldsm_x4t(Bsb + b_off + jj * 2304 + ks * 32, b);
            mma16816(acc[0][2 * jj + 0], a[0], b[0], b[1]);
            mma16816(acc[0][2 * jj + 1], a[0], b[2], b[3]);
            mma16816(acc[1][2 * jj + 0], a[1], b[0], b[1]);
            mma16816(acc[1][2 * jj + 1], a[1], b[2], b[3]);
        }
    }

    #pragma unroll
    for (int mi = 0; mi < 2; mi++) {
        #pragma unroll
        for (int rh = 0; rh < 2; rh++) {
            int m = m_base + mi * 16 + rh * 8 + grp;
            if (m >= 160) continue;
            int side = m / 80, rr = m % 80;
            int slot = (rr < 48) ? rr : (rr < 64 ? 96 + (rr - 48) : 128 + (rr - 64));
            float bias = g_B1[side][rr];
            __nv_bfloat16* dst = &g_Fb[side][n][slot][0];
            #pragma unroll
            for (int nj = 0; nj < 8; nj++) {
                int p = p0 + n_base + nj * 8 + tig * 2;
                if (p < Pp) {
                    __nv_bfloat162 hv = __floats2bfloat162_rn(
                        acc[mi][nj][rh * 2 + 0] + bias,
                        acc[mi][nj][rh * 2 + 1] + bias);
                    *(__nv_bfloat162*)(dst + p) = hv;
                }
            }
        }
    }
}

// ---------------- conv9 via HMMA: PERSISTENT, A staged once per CTA ----------------
#define C9_SMEM (1152 * 144 + 328 * 144)
#define C9_TILES (59 * 64)
__global__ void conv9_hmma_kernel() {
    extern __shared__ __align__(16) char smem[];
    char* As = smem;
    char* Bs = smem + 1152 * 144;
    int tid = threadIdx.x;
    int wid = tid >> 5, lane = tid & 31;
    int g8 = lane >> 3, r8 = lane & 7;
    int grp = lane >> 2, tig = lane & 3;
    int m_base = (wid & 3) * 32;
    int n_base = (wid >> 2) * 64;

    uint32_t Asb = smem_u32(As);
    uint32_t Bsb = smem_u32(Bs);
    uint32_t a_off = (uint32_t)(m_base + ((g8 & 1) << 3) + r8) * 144 + ((g8 >> 1) << 4);
    uint32_t b_off = (uint32_t)(n_base + ((g8 & 2) << 2) + r8) * 144 + ((g8 & 1) << 4);

    const uint4* wsrc = &g_W9h4[0][0][0];
    for (int i = tid; i < 9216; i += 256) {
        int row = i >> 3, ch = i & 7;
        *(uint4*)(As + row * 144 + ch * 16) = wsrc[i];
    }

    for (int t = blockIdx.x; t < C9_TILES; t += gridDim.x) {
        int px = t % 59, n = t / 59;
        int p0 = px * 128;
        __syncthreads();
        const uint4* xh = &g_xTh4[n][0][0];
        for (int i = tid; i < 2624; i += 256) {
            int row = i >> 3, ch = i & 7;
            int p = p0 - 100 + row;
            uint4 v = (p >= 0 && p < Pp) ? xh[(size_t)p * 8 + ch] : make_uint4(0, 0, 0, 0);
            *(uint4*)(Bs + row * 144 + ch * 16) = v;
        }
        __syncthreads();

        float acc[2][8][4];
        #pragma unroll
        for (int mi = 0; mi < 2; mi++)
            #pragma unroll
            for (int nj = 0; nj < 8; nj++)
                #pragma unroll
                for (int e = 0; e < 4; e++) acc[mi][nj][e] = 0.f;

        for (int tap = 0; tap < 9; tap++) {
            uint32_t abase = Asb + tap * 18432 + a_off;
            uint32_t bbase = Bsb + tap * 3600 + b_off;
            #pragma unroll
            for (int ks = 0; ks < 4; ks++) {
                uint32_t a[2][4];
                ldsm_x4(abase + ks * 32, a[0]);
                ldsm_x4(abase + 2304 + ks * 32, a[1]);
                #pragma unroll
                for (int jj = 0; jj < 4; jj++) {
                    uint32_t b[4];
                    ldsm_x4t(bbase + jj * 2304 + ks * 32, b);
                    mma16816(acc[0][2 * jj + 0], a[0], b[0], b[1]);
                    mma16816(acc[0][2 * jj + 1], a[0], b[2], b[3]);
                    mma16816(acc[1][2 * jj + 0], a[1], b[0], b[1]);
                    mma16816(acc[1][2 * jj + 1], a[1], b[2], b[3]);
                }
            }
        }

        #pragma unroll
        for (int mi = 0; mi < 2; mi++) {
            #pragma unroll
            for (int rh = 0; rh < 2; rh++) {
                int m = m_base + mi * 16 + rh * 8 + grp;
                int side = m >> 6, rr = m & 63;
                int slot = (rr < 48) ? 48 + rr : 112 + (rr - 48);
                float bias = g_B9[side][rr];
                __nv_bfloat16* dst = &g_Fb[side][n][slot][0];
                #pragma unroll
                for (int nj = 0; nj < 8; nj++) {
                    int p = p0 + n_base + nj * 8 + tig * 2;
                    if (p < Pp) {
                        __nv_bfloat162 hv = __floats2bfloat162_rn(
                            acc[mi][nj][rh * 2 + 0] + bias,
                            acc[mi][nj][rh * 2 + 1] + bias);
                        *(__nv_bfloat162*)(dst + p) = hv;
                    }
                }
            }
        }
    }
}

// ---------------- gram via HMMA + fused softmax (bf16 F input) ----------------
#define GSTR 24
__global__ void gram_hmma_kernel() {
    __shared__ __align__(16) __nv_bfloat16 f1s[4][32 * GSTR];
    __shared__ __align__(16) __nv_bfloat16 f2s[4][32 * GSTR];
    __shared__ float Msw[4][32 * 32];
    __shared__ float Mt[32 * 32];
    __shared__ float cmax[25], csum[25];

    int a_id = blockIdx.x;
    int n = blockIdx.y;
    int i = a_id / 3, g = a_id % 3;
    int slot0 = (g == 0) ? i * 16 : (g == 1 ? 48 + i * 16 : 96 + i * 16);

    int tid = threadIdx.x;
    int wid = tid >> 5, lane = tid & 31;
    int g8 = lane >> 3, r8 = lane & 7;
    int grp = lane >> 2, tig = lane & 3;

    for (int idx = tid; idx < 4 * 32 * GSTR / 2; idx += 128) {
        ((uint32_t*)f1s)[idx] = 0;
        ((uint32_t*)f2s)[idx] = 0;
    }
    __syncthreads();

    uint32_t f1b = smem_u32(&f1s[wid][0]);
    uint32_t f2b = smem_u32(&f2s[wid][0]);
    uint32_t a_off = (uint32_t)(((g8 & 1) << 3) + r8) * 48 + ((g8 >> 1) << 4);
    uint32_t b_off = (uint32_t)(((g8 & 2) << 2) + r8) * 48 + ((g8 & 1) << 4);

    float acc[2][4][4];
    #pragma unroll
    for (int mi = 0; mi < 2; mi++)
        #pragma unroll
        for (int nj = 0; nj < 4; nj++)
            #pragma unroll
            for (int e = 0; e < 4; e++) acc[mi][nj][e] = 0.f;

    const __nv_bfloat16 z16 = __float2bfloat16_rn(0.f);
    for (int icl = 0; icl < 4; icl++) {
        int ic = wid * 4 + icl;
        const __nv_bfloat16* src1 = &g_Fb[0][n][slot0 + ic][0];
        const __nv_bfloat16* src2 = &g_Fb[1][n][slot0 + ic][0];
        for (int chunk = 0; chunk < 19; chunk++) {
            int t0 = chunk * 16;
            int elems = (300 - t0 >= 16) ? 400 : (300 - t0) * 25;
            int base = t0 * 25;
            __syncwarp();
            for (int idx = lane; idx < 400; idx += 32) {
                __nv_bfloat16 v1 = (idx < elems) ? src1[base + idx] : z16;
                __nv_bfloat16 v2 = (idx < elems) ? src2[base + idx] : z16;
                int tt = idx / 25, u = idx % 25;
                f1s[wid][u * GSTR + tt] = v1;
                f2s[wid][u * GSTR + tt] = v2;
            }
            __syncwarp();
            uint32_t a[2][4];
            ldsm_x4(f1b + a_off, a[0]);
            ldsm_x4(f1b + a_off + 16 * 48, a[1]);
            #pragma unroll
            for (int nj2 = 0; nj2 < 2; nj2++) {
                uint32_t b[4];
                ldsm_x4t(f2b + b_off + nj2 * 16 * 48, b);
                mma16816(acc[0][2 * nj2 + 0], a[0], b[0], b[1]);
                mma16816(acc[0][2 * nj2 + 1], a[0], b[2], b[3]);
                mma16816(acc[1][2 * nj2 + 0], a[1], b[0], b[1]);
                mma16816(acc[1][2 * nj2 + 1], a[1], b[2], b[3]);
            }
        }
    }

    #pragma unroll
    for (int mi = 0; mi < 2; mi++)
        #pragma unroll
        for (int nj = 0; nj < 4; nj++) {
            int u0 = mi * 16 + grp;
            int v0 = nj * 8 + tig * 2;
            Msw[wid][u0 * 32 + v0]       = acc[mi][nj][0];
            Msw[wid][u0 * 32 + v0 + 1]   = acc[mi][nj][1];
            Msw[wid][(u0 + 8) * 32 + v0]     = acc[mi][nj][2];
            Msw[wid][(u0 + 8) * 32 + v0 + 1] = acc[mi][nj][3];
        }
    __syncthreads();
    for (int cell = tid; cell < 1024; cell += 128) {
        float s = Msw[0][cell] + Msw[1][cell] + Msw[2][cell] + Msw[3][cell];
        Mt[cell] = s / 4800.f;
    }
    __syncthreads();
    if (tid < 25) {
        float m = -1e30f;
        for (int uu = 0; uu < 25; uu++) m = fmaxf(m, Mt[uu * 32 + tid]);
        float s = 0.f;
        for (int uu = 0; uu < 25; uu++) s += expf(Mt[uu * 32 + tid] - m);
        cmax[tid] = m; csum[tid] = s;
    }
    __syncthreads();
    for (int cell = tid; cell < 625; cell += 128) {
        int u = cell / 25, v = cell % 25;
        g_S[n][a_id][u][v] = expf(Mt[u * 32 + v] - cmax[v]) / csum[v];
    }
}

// ---------------- combine ----------------
__global__ void combine_kernel(const float* weights) {
    int n = blockIdx.x;
    float w5 = weights[5], w6 = weights[6], w7 = weights[7];
    float* Ain = &g_Ai[n][0][0][0];
    const float* Sn = &g_S[n][0][0][0];
    for (int idx = threadIdx.x; idx < 3 * 625; idx += blockDim.x) {
        int i = idx / 625, uv = idx % 625;
        Ain[idx] = (&g_Amix[0][0][0])[i * 625 + uv]
                 + w5 * Sn[(i * 3 + 0) * 625 + uv]
                 + w6 * Sn[(i * 3 + 1) * 625 + uv]
                 + w7 * Sn[(i * 3 + 2) * 625 + uv];
    }
}

// ---------------- z = x_flat @ Ai : x staged once, all 3 subsets per block ----------------
#define Z3_SMEM ((12800 + 1875 + 12800) * 4)
__global__ void z_kernel3(const float* __restrict__ x) {
    extern __shared__ float dyn[];
    float* xs = dyn;             // 12800
    float* As = dyn + 12800;     // 3 x 625
    float* zs = dyn + 14675;     // 12800
    int blk = blockIdx.x;
    int n = blockIdx.y;
    int tid = threadIdx.x;

    for (int idx = tid; idx < 1875; idx += 256) As[idx] = (&g_Ai[n][0][0][0])[idx];
    const float* xn = x + (size_t)n * Cc * Pp;
    int gbase = blk * 12800;
    for (int idx = tid; idx < 12800; idx += 256) {
        int gi = gbase + idx;
        xs[idx] = (gi < Cc * Pp) ? xn[gi] : 0.f;
    }
    __syncthreads();

    int r0 = tid, r1 = tid + 256;
    for (int i = 0; i < 3; i++) {
        float acc0[25], acc1[25];
        #pragma unroll
        for (int v = 0; v < 25; v++) { acc0[v] = 0.f; acc1[v] = 0.f; }
        const float* Ai = As + i * 625;
        for (int u = 0; u < 25; u++) {
            float x0 = xs[r0 * 25 + u];
            float x1 = xs[r1 * 25 + u];
            #pragma unroll
            for (int v = 0; v < 25; v++) {
                float av = Ai[u * 25 + v];
                acc0[v] += av * x0;
                acc1[v] += av * x1;
            }
        }
        #pragma unroll
        for (int v = 0; v < 25; v++) {
            zs[r0 * 25 + v] = acc0[v];
            zs[r1 * 25 + v] = acc1[v];
        }
        __syncthreads();
        float* zn = &g_z[n][i][0][0];
        for (int idx = tid; idx < 12800; idx += 256) {
            int gi = gbase + idx;
            if (gi < Cc * Pp) zn[gi] = zs[idx];
        }
        __syncthreads();
    }
}

// ---------------- dconv (fp32, known-good) ----------------
#define PTD 96
__global__ void dconv_kernel(const float* __restrict__ d_w, const float* __restrict__ d_b) {
    int p0 = blockIdx.x * PTD;
    int n = blockIdx.y;
    __shared__ float ws[Cc][32];
    __shared__ float zs[32][PTD];
    int ty = threadIdx.y, tx = threadIdx.x;
    int tid = ty * 16 + tx;
    float acc[4][6];
    #pragma unroll
    for (int rr = 0; rr < 4; rr++)
        #pragma unroll
        for (int jj = 0; jj < 6; jj++) acc[rr][jj] = 0.f;
    const float* zn = &g_z[n][0][0][0];
    for (int kc = 0; kc < 6; kc++) {
        __syncthreads();
        for (int idx = tid; idx < Cc * 32; idx += 256) {
            int o = idx / 32, k32 = idx % 32;
            int kk = kc * 32 + k32;
            int i = kk / 64, c = kk % 64;
            ws[o][k32] = d_w[(i * 64 + o) * 64 + c];
        }
        for (int idx = tid; idx < 32 * PTD; idx += 256) {
            int k32 = idx / PTD, pc = idx % PTD;
            int kk = kc * 32 + k32;
            int p = p0 + pc;
            zs[k32][pc] = (p < Pp) ? zn[(size_t)kk * Pp + p] : 0.f;
        }
        __syncthreads();
        #pragma unroll
        for (int k32 = 0; k32 < 32; k32++) {
            float wv[4];
            #pragma unroll
            for (int rr = 0; rr < 4; rr++) wv[rr] = ws[ty + 16 * rr][k32];
            #pragma unroll
            for (int jj = 0; jj < 6; jj++) {
                float zv = zs[k32][tx + 16 * jj];
                #pragma unroll
                for (int rr = 0; rr < 4; rr++) acc[rr][jj] += wv[rr] * zv;
            }
        }
    }
    #pragma unroll
    for (int rr = 0; rr < 4; rr++) {
        int o = ty + 16 * rr;
        float b = d_b[o] + d_b[64 + o] + d_b[128 + o];
        #pragma unroll
        for (int jj = 0; jj < 6; jj++) {
            int p = p0 + tx + 16 * jj;
            if (p < Pp) g_y[n][o][p] = acc[rr][jj] + b;
        }
    }
}

// ---------------- BatchNorm (vectorized stage 1) ----------------
__global__ void bnstat1_kernel() {
    int o = blockIdx.x, n = blockIdx.y;
    const float4* yr = (const float4*)&g_y[n][o][0];
    float s = 0.f, s2 = 0.f;
    for (int q = threadIdx.x; q < Pp / 4; q += 256) {
        float4 v = yr[q];
        s  += v.x + v.y + v.z + v.w;
        s2 += v.x * v.x + v.y * v.y + v.z * v.z + v.w * v.w;
    }
    __shared__ float rs[256], rs2[256];
    rs[threadIdx.x] = s; rs2[threadIdx.x] = s2;
    __syncthreads();
    for (int st = 128; st > 0; st >>= 1) {
        if (threadIdx.x < st) {
            rs[threadIdx.x] += rs[threadIdx.x + st];
            rs2[threadIdx.x] += rs2[threadIdx.x + st];
        }
        __syncthreads();
    }
    if (threadIdx.x == 0) { g_part[o][n][0] = rs[0]; g_part[o][n][1] = rs2[0]; }
}

__global__ void bnstat2_kernel(const float* bn_w, const float* bn_b) {
    int o = blockIdx.x;
    __shared__ float rs[64], rs2[64];
    rs[threadIdx.x]  = g_part[o][threadIdx.x][0];
    rs2[threadIdx.x] = g_part[o][threadIdx.x][1];
    __syncthreads();
    for (int st = 32; st > 0; st >>= 1) {
        if (threadIdx.x < st) {
            rs[threadIdx.x] += rs[threadIdx.x + st];
            rs2[threadIdx.x] += rs2[threadIdx.x + st];
        }
        __syncthreads();
    }
    if (threadIdx.x == 0) {
        float M = (float)Nn * (float)Pp;
        float mu = rs[0] / M;
        float var = rs2[0] / M - mu * mu;
        float scale = bn_w[o] * rsqrtf(var + 1e-5f);
        g_bn[o][0] = scale;
        g_bn[o][1] = bn_b[o] - mu * scale;
    }
}

__global__ void final_kernel(const float* __restrict__ x, float* __restrict__ out) {
    size_t idx = (size_t)blockIdx.x * blockDim.x + threadIdx.x;   // float4 index
    size_t total4 = (size_t)Nn * Cc * Pp / 4;
    if (idx >= total4) return;
    int c = (int)((idx * 4 / Pp) % Cc);
    float sc = g_bn[c][0], sh = g_bn[c][1];
    float4 yv = ((const float4*)&g_y[0][0][0])[idx];
    float4 xv = ((const float4*)x)[idx];
    float4 r;
    r.x = fmaxf(yv.x * sc + sh + xv.x, 0.f);
    r.y = fmaxf(yv.y * sc + sh + xv.y, 0.f);
    r.z = fmaxf(yv.z * sc + sh + xv.z, 0.f);
    r.w = fmaxf(yv.w * sc + sh + xv.w, 0.f);
    ((float4*)out)[idx] = r;
}

// ---------------- launch ----------------
extern "C" void kernel_launch(void* const* d_in, const int* in_sizes, int n_in,
                              void* d_out, int out_size) {
    const float* x        = (const float*)d_in[0];
    const float* weights  = (const float*)d_in[1];
    const float* A        = (const float*)d_in[2];
    const float* a_w      = (const float*)d_in[3];
    const float* a_b      = (const float*)d_in[4];
    const float* b_w      = (const float*)d_in[5];
    const float* b_b      = (const float*)d_in[6];
    const float* d_w      = (const float*)d_in[7];
    const float* d_b      = (const float*)d_in[8];
    const float* t1_w     = (const float*)d_in[9];
    const float* t1_b     = (const float*)d_in[10];
    const float* t2_w     = (const float*)d_in[11];
    const float* t2_b     = (const float*)d_in[12];
    const float* st11_w1x1= (const float*)d_in[13];
    const float* st11_w9  = (const float*)d_in[14];
    const float* st11_b   = (const float*)d_in[15];
    const float* st12_w1x1= (const float*)d_in[16];
    const float* st12_w9  = (const float*)d_in[17];
    const float* st12_b   = (const float*)d_in[18];
    const float* bn_w     = (const float*)d_in[19];
    const float* bn_b     = (const float*)d_in[20];
    float* out = (float*)d_out;

    cudaFuncSetAttribute(z_kernel3, cudaFuncAttributeMaxDynamicSharedMemorySize, Z3_SMEM);
    cudaFuncSetAttribute(conv9_hmma_kernel, cudaFuncAttributeMaxDynamicSharedMemorySize, C9_SMEM);

    pack_kernel<<<64, 256>>>(a_w, a_b, b_w, b_b, t1_b, t2_b,
                             st11_w1x1, st11_b, st12_w1x1, st12_b);
    w9pack_kernel<<<(9 * 128 * 64 + 255) / 256, 256>>>(t1_w, t2_w, st11_w9, st12_w9);
    w1bpack_kernel<<<(192 * 64 + 255) / 256, 256>>>();
    xsplit_kernel<<<dim3(118, 64), 256>>>(x);
    amix_kernel<<<3, 625>>>(A, weights);
    conv1x1_hmma_kernel<<<dim3(59, 64), 384>>>();
    conv9_hmma_kernel<<<148, 256, C9_SMEM>>>();
    gram_hmma_kernel<<<dim3(9, 64), 128>>>();
    combine_kernel<<<64, 1024>>>(weights);
    z_kernel3<<<dim3(38, 64), 256, Z3_SMEM>>>(x);
    dconv_kernel<<<dim3(79, 64), dim3(16, 16)>>>(d_w, d_b);
    bnstat1_kernel<<<dim3(64, 64), 256>>>();
    bnstat2_kernel<<<64, 64>>>(bn_w, bn_b);
    final_kernel<<<(Nn * Cc * Pp / 4 + 255) / 256, 256>>>(x, out);
}